// round 8
// baseline (speedup 1.0000x reference)
#include <cuda_runtime.h>
#include <cuda_fp16.h>

// Problem constants (fixed by the reference: B=64, N=10000, E=320000)
#define BB 64
#define NMAX 10000
#define EMAX 320000
#define LAMBDA_PHY 0.3

// Node storage: per node, 32 lanes x {half2 p-pair, half2 q-pair} = 256B/node row.
struct NodePair { __half2 p; __half2 q; };   // 8 bytes
__device__ NodePair g_nodes[NMAX * 32];
// Packed edge metadata: {src | dst<<16, half2(c0,c1), half2(c2,c2), pad}
__device__ uint4    g_edgeMeta[EMAX];
__device__ float    g_dataPart[2048];
__device__ float    g_phyPart[4096];
__device__ unsigned g_done = 0;

static __device__ __forceinline__ __half2 u2h(unsigned u) {
    return *reinterpret_cast<const __half2*>(&u);
}
static __device__ __forceinline__ unsigned h2u(__half2 h) {
    return *reinterpret_cast<const unsigned*>(&h);
}

// ---------------------------------------------------------------------------
// Kernel A: transpose [B,N] -> node-major fp16 interleaved [N][32]{p2,q2},
//           fused data-loss partials, per-block edge dtype probe,
//           fused edge-metadata packing (grid-stride over E).
// grid = ceil(N/32), block = (32, 8)
// ---------------------------------------------------------------------------
__global__ void prep_kernel(const float* __restrict__ pred,
                            const float* __restrict__ target,
                            const float* __restrict__ prev,
                            const float* __restrict__ c0,
                            const float* __restrict__ c1,
                            const float* __restrict__ c2,
                            const void* __restrict__ ei,
                            int N, int E) {
    __shared__ float tp[BB][33];
    __shared__ float tq[BB][33];
    __shared__ float red[256];
    __shared__ int   s_is64;

    const int tx = threadIdx.x;     // 0..31
    const int ty = threadIdx.y;     // 0..7
    const int n0 = blockIdx.x * 32;

    // dtype probe: odd int32 words of first 32 "int64" slots all zero iff int64
    if (ty == 0) {
        int v = ((const int*)ei)[2 * tx + 1];
        unsigned b = __ballot_sync(0xffffffffu, v != 0);
        if (tx == 0) s_is64 = (b == 0) ? 1 : 0;
    }

    const int n = n0 + tx;
    const bool valid = (n < N);
    float acc = 0.0f;

    #pragma unroll
    for (int jb = 0; jb < BB; jb += 8) {
        int b = jb + ty;
        if (valid) {
            float p = pred[b * N + n];
            float t = target[b * N + n];
            float q = prev[b * N + n];
            float d = p - t;
            acc = fmaf(d, d, acc);
            tp[b][tx] = p;
            tq[b][tx] = q;
        }
    }
    __syncthreads();        // also publishes s_is64

    // write phase: tx = batch-pair index (0..31), coalesced 256B node rows
    #pragma unroll
    for (int jn = 0; jn < 32; jn += 8) {
        int nl = jn + ty;
        int node = n0 + nl;
        if (node < N) {
            __half2 ph = __floats2half2_rn(tp[2 * tx][nl], tp[2 * tx + 1][nl]);
            __half2 qh = __floats2half2_rn(tq[2 * tx][nl], tq[2 * tx + 1][nl]);
            NodePair np; np.p = ph; np.q = qh;
            g_nodes[node * 32 + tx] = np;
        }
    }

    // deterministic block reduction of data-loss partial
    int tid = ty * 32 + tx;
    red[tid] = acc;
    __syncthreads();
    #pragma unroll
    for (int s = 128; s > 0; s >>= 1) {
        if (tid < s) red[tid] += red[tid + s];
        __syncthreads();
    }
    if (tid == 0) g_dataPart[blockIdx.x] = red[0];

    // -------- edge metadata packing (grid-stride over E) --------
    const int is64 = s_is64;
    const long long* __restrict__ ei64 = (const long long*)ei;
    const int*       __restrict__ ei32 = (const int*)ei;
    const int gtid   = blockIdx.x * 256 + tid;
    const int stride = gridDim.x * 256;
    for (int e = gtid; e < E; e += stride) {
        int s, d;
        if (is64) { s = (int)ei64[e]; d = (int)ei64[E + e]; }
        else      { s = ei32[e];      d = ei32[E + e]; }
        uint4 m;
        m.x = (unsigned)s | ((unsigned)d << 16);
        m.y = h2u(__floats2half2_rn(c0[e], c1[e]));
        m.z = h2u(__float2half2_rn(c2[e]));
        m.w = 0u;
        g_edgeMeta[e] = m;
    }
}

// ---------------------------------------------------------------------------
// Kernel B: physics residual + fused final reduce.
// Quarter-warp (8 lanes) per edge => 4 edges per warp-iteration.
// Per iteration: 1 metadata LDG.128 + 4 fully-coalesced node LDG.128.
// Zero shuffles. r^2 accumulated in TWO half2 chains, flushed every 8 values.
// Grid sized for exactly ONE 32-edge group per warp (10000 warps).
// ---------------------------------------------------------------------------
__global__ void __launch_bounds__(256)
edge_phy_kernel(int E, int N, int nDataBlocks, float* __restrict__ out) {
    const int lane    = threadIdx.x & 31;
    const int quarter = lane >> 3;          // 0..3 : which edge of the 4
    const int ql      = lane & 7;           // lane within quarter
    const int warp    = (blockIdx.x * blockDim.x + threadIdx.x) >> 5;
    const int nwarps  = (gridDim.x * blockDim.x) >> 5;

    const uint4* __restrict__ nodes4 = (const uint4*)g_nodes;   // 16 per node
    const uint4* __restrict__ meta   = g_edgeMeta;

    float acc0 = 0.0f, acc1 = 0.0f;
    const int ngroups = (E + 31) >> 5;

    for (int g = warp; g < ngroups; g += nwarps) {
        const int base = g << 5;
        const int m = min(32, E - base);

        if (m == 32) {
            #pragma unroll 2
            for (int jj = 0; jj < 4; ++jj) {
                __half2 hacc0 = __float2half2_rn(0.0f);
                __half2 hacc1 = __float2half2_rn(0.0f);
                #pragma unroll
                for (int j2 = 0; j2 < 2; ++j2) {
                    const int eslot = jj * 8 + j2 * 4 + quarter;    // 0..31
                    const uint4 mt = __ldg(meta + base + eslot);
                    const int ss = (int)(mt.x & 0xFFFFu);
                    const int dd = (int)(mt.x >> 16);

                    const uint4* sp = nodes4 + ss * 16 + ql;
                    const uint4* dp = nodes4 + dd * 16 + ql;
                    uint4 rs0 = __ldg(sp);
                    uint4 rs1 = __ldg(sp + 8);
                    uint4 rd0 = __ldg(dp);
                    uint4 rd1 = __ldg(dp + 8);

                    __half2 c01 = u2h(mt.y);
                    __half2 b0 = __half2half2(__low2half(c01));
                    __half2 b1 = __half2half2(__high2half(c01));
                    __half2 b2 = u2h(mt.z);

                    __half2 t, r;
                    t = __hmul2(b2, u2h(rd0.y));
                    t = __hfma2(b1, u2h(rs0.y), t);
                    t = __hfma2(b0, u2h(rs0.x), t);
                    r = __hsub2(u2h(rd0.x), t);
                    hacc0 = __hfma2(r, r, hacc0);

                    t = __hmul2(b2, u2h(rd0.w));
                    t = __hfma2(b1, u2h(rs0.w), t);
                    t = __hfma2(b0, u2h(rs0.z), t);
                    r = __hsub2(u2h(rd0.z), t);
                    hacc1 = __hfma2(r, r, hacc1);

                    t = __hmul2(b2, u2h(rd1.y));
                    t = __hfma2(b1, u2h(rs1.y), t);
                    t = __hfma2(b0, u2h(rs1.x), t);
                    r = __hsub2(u2h(rd1.x), t);
                    hacc0 = __hfma2(r, r, hacc0);

                    t = __hmul2(b2, u2h(rd1.w));
                    t = __hfma2(b1, u2h(rs1.w), t);
                    t = __hfma2(b0, u2h(rs1.z), t);
                    r = __hsub2(u2h(rd1.z), t);
                    hacc1 = __hfma2(r, r, hacc1);
                }
                float2 f0 = __half22float2(hacc0);
                float2 f1 = __half22float2(hacc1);
                acc0 += f0.x + f1.x;
                acc1 += f0.y + f1.y;
            }
        } else {
            // cold tail (E % 32 != 0): fp32 math, per-slot guard
            for (int eslot = quarter; eslot < m; eslot += 4) {
                const uint4 mt = __ldg(meta + base + eslot);
                const int ss = (int)(mt.x & 0xFFFFu);
                const int dd = (int)(mt.x >> 16);
                const uint4* sp = nodes4 + ss * 16 + ql;
                const uint4* dp = nodes4 + dd * 16 + ql;
                uint4 rsA[2] = { __ldg(sp), __ldg(sp + 8) };
                uint4 rdA[2] = { __ldg(dp), __ldg(dp + 8) };
                __half2 c01 = u2h(mt.y);
                float b0 = __half2float(__low2half(c01));
                float b1 = __half2float(__high2half(c01));
                float b2 = __half2float(__low2half(u2h(mt.z)));
                #pragma unroll
                for (int h = 0; h < 2; ++h) {
                    float2 ps0 = __half22float2(u2h(rsA[h].x));
                    float2 qs0 = __half22float2(u2h(rsA[h].y));
                    float2 pd0 = __half22float2(u2h(rdA[h].x));
                    float2 qd0 = __half22float2(u2h(rdA[h].y));
                    float2 ps1 = __half22float2(u2h(rsA[h].z));
                    float2 qs1 = __half22float2(u2h(rsA[h].w));
                    float2 pd1 = __half22float2(u2h(rdA[h].z));
                    float2 qd1 = __half22float2(u2h(rdA[h].w));
                    float r;
                    r = pd0.x - fmaf(b0, ps0.x, fmaf(b1, qs0.x, b2 * qd0.x)); acc0 = fmaf(r, r, acc0);
                    r = pd0.y - fmaf(b0, ps0.y, fmaf(b1, qs0.y, b2 * qd0.y)); acc1 = fmaf(r, r, acc1);
                    r = pd1.x - fmaf(b0, ps1.x, fmaf(b1, qs1.x, b2 * qd1.x)); acc0 = fmaf(r, r, acc0);
                    r = pd1.y - fmaf(b0, ps1.y, fmaf(b1, qs1.y, b2 * qd1.y)); acc1 = fmaf(r, r, acc1);
                }
            }
        }
    }

    // deterministic block reduction
    __shared__ float red[256];
    __shared__ unsigned isLast;
    const int tid = threadIdx.x;
    red[tid] = acc0 + acc1;
    __syncthreads();
    #pragma unroll
    for (int sOff = 128; sOff > 0; sOff >>= 1) {
        if (tid < sOff) red[tid] += red[tid + sOff];
        __syncthreads();
    }
    if (tid == 0) {
        g_phyPart[blockIdx.x] = red[0];
        __threadfence();
        unsigned v = atomicAdd(&g_done, 1u);
        isLast = (v == gridDim.x - 1) ? 1u : 0u;
    }
    __syncthreads();

    if (isLast) {
        __shared__ double rd2[256];
        __shared__ double rp2[256];
        double sd = 0.0, sp = 0.0;
        for (int i = tid; i < nDataBlocks; i += 256) sd += (double)g_dataPart[i];
        for (int i = tid; i < (int)gridDim.x; i += 256) sp += (double)g_phyPart[i];
        rd2[tid] = sd;
        rp2[tid] = sp;
        __syncthreads();
        #pragma unroll
        for (int sOff = 128; sOff > 0; sOff >>= 1) {
            if (tid < sOff) { rd2[tid] += rd2[tid + sOff]; rp2[tid] += rp2[tid + sOff]; }
            __syncthreads();
        }
        if (tid == 0) {
            double data_loss = rd2[0] / ((double)BB * (double)N);
            double phy_loss  = rp2[0] / ((double)BB * (double)E);
            double total = data_loss + LAMBDA_PHY * phy_loss;
            out[0] = (float)total;
            out[1] = (float)data_loss;
            out[2] = (float)phy_loss;
            g_done = 0;   // reset for next graph replay
        }
    }
}

extern "C" void kernel_launch(void* const* d_in, const int* in_sizes, int n_in,
                              void* d_out, int out_size) {
    const float* pred   = (const float*)d_in[0];
    const float* target = (const float*)d_in[1];
    const float* prev   = (const float*)d_in[2];
    const float* c0     = (const float*)d_in[3];
    const float* c1     = (const float*)d_in[4];
    const float* c2     = (const float*)d_in[5];
    const void*  ei     = d_in[6];

    const int N = in_sizes[0] / BB;     // 10000
    const int E = in_sizes[3];          // 320000

    dim3 tb(32, 8);
    int nDataBlocks = (N + 31) / 32;    // 313
    prep_kernel<<<nDataBlocks, tb>>>(pred, target, prev, c0, c1, c2, ei, N, E);

    // exactly ONE group per warp: blocks = ceil(ngroups / 8)
    int ngroups = (E + 31) / 32;            // 10000
    int phyBlocks = (ngroups + 7) / 8;      // 1250
    if (phyBlocks > 4096) phyBlocks = 4096;
    edge_phy_kernel<<<phyBlocks, 256>>>(E, N, nDataBlocks, (float*)d_out);
}

// round 9
// speedup vs baseline: 1.0922x; 1.0922x over previous
#include <cuda_runtime.h>
#include <cuda_fp16.h>

// Problem constants (fixed by the reference: B=64, N=10000, E=320000)
#define BB 64
#define NMAX 10000
#define EMAX 320000
#define LAMBDA_PHY 0.3

// Node storage: per node, 32 lanes x {half2 p-pair, half2 q-pair} = 256B/node row.
struct NodePair { __half2 p; __half2 q; };   // 8 bytes
__device__ NodePair g_nodes[NMAX * 32];
// Packed edge metadata: {src | dst<<16, half2(c0,c1), half2(c2,c2), pad}
__device__ uint4    g_edgeMeta[EMAX];
__device__ float    g_dataPart[2048];
__device__ float    g_phyPart[4096];
__device__ unsigned g_done = 0;

static __device__ __forceinline__ __half2 u2h(unsigned u) {
    return *reinterpret_cast<const __half2*>(&u);
}
static __device__ __forceinline__ unsigned h2u(__half2 h) {
    return *reinterpret_cast<const unsigned*>(&h);
}

// ---------------------------------------------------------------------------
// Kernel A: transpose [B,N] -> node-major fp16 interleaved [N][32]{p2,q2},
//           fused data-loss partials, per-block edge dtype probe,
//           fused edge-metadata packing (grid-stride over E).
// grid = ceil(N/32), block = (32, 8)
// ---------------------------------------------------------------------------
__global__ void prep_kernel(const float* __restrict__ pred,
                            const float* __restrict__ target,
                            const float* __restrict__ prev,
                            const float* __restrict__ c0,
                            const float* __restrict__ c1,
                            const float* __restrict__ c2,
                            const void* __restrict__ ei,
                            int N, int E) {
    __shared__ float tp[BB][33];
    __shared__ float tq[BB][33];
    __shared__ float red[256];
    __shared__ int   s_is64;

    const int tx = threadIdx.x;     // 0..31
    const int ty = threadIdx.y;     // 0..7
    const int n0 = blockIdx.x * 32;

    // dtype probe: odd int32 words of first 32 "int64" slots all zero iff int64
    if (ty == 0) {
        int v = ((const int*)ei)[2 * tx + 1];
        unsigned b = __ballot_sync(0xffffffffu, v != 0);
        if (tx == 0) s_is64 = (b == 0) ? 1 : 0;
    }

    const int n = n0 + tx;
    const bool valid = (n < N);
    float acc = 0.0f;

    #pragma unroll
    for (int jb = 0; jb < BB; jb += 8) {
        int b = jb + ty;
        if (valid) {
            float p = pred[b * N + n];
            float t = target[b * N + n];
            float q = prev[b * N + n];
            float d = p - t;
            acc = fmaf(d, d, acc);
            tp[b][tx] = p;
            tq[b][tx] = q;
        }
    }
    __syncthreads();        // also publishes s_is64

    // write phase: tx = batch-pair index (0..31), coalesced 256B node rows
    #pragma unroll
    for (int jn = 0; jn < 32; jn += 8) {
        int nl = jn + ty;
        int node = n0 + nl;
        if (node < N) {
            __half2 ph = __floats2half2_rn(tp[2 * tx][nl], tp[2 * tx + 1][nl]);
            __half2 qh = __floats2half2_rn(tq[2 * tx][nl], tq[2 * tx + 1][nl]);
            NodePair np; np.p = ph; np.q = qh;
            g_nodes[node * 32 + tx] = np;
        }
    }

    // deterministic block reduction of data-loss partial
    int tid = ty * 32 + tx;
    red[tid] = acc;
    __syncthreads();
    #pragma unroll
    for (int s = 128; s > 0; s >>= 1) {
        if (tid < s) red[tid] += red[tid + s];
        __syncthreads();
    }
    if (tid == 0) g_dataPart[blockIdx.x] = red[0];

    // -------- edge metadata packing (grid-stride over E) --------
    const int is64 = s_is64;
    const long long* __restrict__ ei64 = (const long long*)ei;
    const int*       __restrict__ ei32 = (const int*)ei;
    const int gtid   = blockIdx.x * 256 + tid;
    const int stride = gridDim.x * 256;
    for (int e = gtid; e < E; e += stride) {
        int s, d;
        if (is64) { s = (int)ei64[e]; d = (int)ei64[E + e]; }
        else      { s = ei32[e];      d = ei32[E + e]; }
        uint4 m;
        m.x = (unsigned)s | ((unsigned)d << 16);
        m.y = h2u(__floats2half2_rn(c0[e], c1[e]));
        m.z = h2u(__float2half2_rn(c2[e]));
        m.w = 0u;
        g_edgeMeta[e] = m;
    }
}

// ---------------------------------------------------------------------------
// Kernel B: physics residual + fused final reduce.
// Flat work space of 4-edge quanta (quarter-warp per edge). Balanced
// contiguous chunks: 888 blocks x 8 warps = 7104 warps, 11-12 quanta each
// => single wave at 6 blocks/SM (launch_bounds-forced <=40 regs).
// Per quantum: 1 metadata LDG.128 + 4 coalesced node LDG.128 per lane.
// Zero shuffles. r^2 in two half2 chains flushed every 2 quanta (4 vals/slot).
// ---------------------------------------------------------------------------
__global__ void __launch_bounds__(256, 6)
edge_phy_kernel(int E, int N, int nDataBlocks, float* __restrict__ out) {
    const int lane    = threadIdx.x & 31;
    const int quarter = lane >> 3;          // 0..3 : which edge of the 4
    const int ql      = lane & 7;           // lane within quarter
    const int warp    = (blockIdx.x * blockDim.x + threadIdx.x) >> 5;
    const int nwarps  = (gridDim.x * blockDim.x) >> 5;

    const uint4* __restrict__ nodes4 = (const uint4*)g_nodes;   // 16 per node
    const uint4* __restrict__ meta   = g_edgeMeta;

    float acc0 = 0.0f, acc1 = 0.0f;

    // balanced contiguous chunk over quanta
    const int Q   = (E + 3) >> 2;                 // 80000
    const int K   = Q / nwarps;                   // 11
    const int rem = Q - K * nwarps;               // 1856
    int i    = warp * K + min(warp, rem);
    int iend = i + K + (warp < rem ? 1 : 0);

    // bulk: pairs of full quanta
    for (; i + 2 <= iend && ((i + 2) << 2) <= E; i += 2) {
        __half2 hacc0 = __float2half2_rn(0.0f);
        __half2 hacc1 = __float2half2_rn(0.0f);
        #pragma unroll
        for (int j = 0; j < 2; ++j) {
            const int e = ((i + j) << 2) + quarter;
            const uint4 mt = __ldg(meta + e);
            const int ss = (int)(mt.x & 0xFFFFu);
            const int dd = (int)(mt.x >> 16);

            const uint4* sp = nodes4 + ss * 16 + ql;
            const uint4* dp = nodes4 + dd * 16 + ql;
            uint4 rs0 = __ldg(sp);
            uint4 rs1 = __ldg(sp + 8);
            uint4 rd0 = __ldg(dp);
            uint4 rd1 = __ldg(dp + 8);

            __half2 c01 = u2h(mt.y);
            __half2 b0 = __half2half2(__low2half(c01));
            __half2 b1 = __half2half2(__high2half(c01));
            __half2 b2 = u2h(mt.z);

            __half2 t, r;
            t = __hmul2(b2, u2h(rd0.y));
            t = __hfma2(b1, u2h(rs0.y), t);
            t = __hfma2(b0, u2h(rs0.x), t);
            r = __hsub2(u2h(rd0.x), t);
            hacc0 = __hfma2(r, r, hacc0);

            t = __hmul2(b2, u2h(rd0.w));
            t = __hfma2(b1, u2h(rs0.w), t);
            t = __hfma2(b0, u2h(rs0.z), t);
            r = __hsub2(u2h(rd0.z), t);
            hacc1 = __hfma2(r, r, hacc1);

            t = __hmul2(b2, u2h(rd1.y));
            t = __hfma2(b1, u2h(rs1.y), t);
            t = __hfma2(b0, u2h(rs1.x), t);
            r = __hsub2(u2h(rd1.x), t);
            hacc0 = __hfma2(r, r, hacc0);

            t = __hmul2(b2, u2h(rd1.w));
            t = __hfma2(b1, u2h(rs1.w), t);
            t = __hfma2(b0, u2h(rs1.z), t);
            r = __hsub2(u2h(rd1.z), t);
            hacc1 = __hfma2(r, r, hacc1);
        }
        float2 f0 = __half22float2(hacc0);
        float2 f1 = __half22float2(hacc1);
        acc0 += f0.x + f1.x;
        acc1 += f0.y + f1.y;
    }

    // leftovers: single quanta (possibly the partial last one) — fp32 math
    for (; i < iend; ++i) {
        const int e = (i << 2) + quarter;
        if (e < E) {
            const uint4 mt = __ldg(meta + e);
            const int ss = (int)(mt.x & 0xFFFFu);
            const int dd = (int)(mt.x >> 16);
            const uint4* sp = nodes4 + ss * 16 + ql;
            const uint4* dp = nodes4 + dd * 16 + ql;
            uint4 rsA[2] = { __ldg(sp), __ldg(sp + 8) };
            uint4 rdA[2] = { __ldg(dp), __ldg(dp + 8) };
            __half2 c01 = u2h(mt.y);
            float b0 = __half2float(__low2half(c01));
            float b1 = __half2float(__high2half(c01));
            float b2 = __half2float(__low2half(u2h(mt.z)));
            #pragma unroll
            for (int h = 0; h < 2; ++h) {
                float2 ps0 = __half22float2(u2h(rsA[h].x));
                float2 qs0 = __half22float2(u2h(rsA[h].y));
                float2 pd0 = __half22float2(u2h(rdA[h].x));
                float2 qd0 = __half22float2(u2h(rdA[h].y));
                float2 ps1 = __half22float2(u2h(rsA[h].z));
                float2 qs1 = __half22float2(u2h(rsA[h].w));
                float2 pd1 = __half22float2(u2h(rdA[h].z));
                float2 qd1 = __half22float2(u2h(rdA[h].w));
                float r;
                r = pd0.x - fmaf(b0, ps0.x, fmaf(b1, qs0.x, b2 * qd0.x)); acc0 = fmaf(r, r, acc0);
                r = pd0.y - fmaf(b0, ps0.y, fmaf(b1, qs0.y, b2 * qd0.y)); acc1 = fmaf(r, r, acc1);
                r = pd1.x - fmaf(b0, ps1.x, fmaf(b1, qs1.x, b2 * qd1.x)); acc0 = fmaf(r, r, acc0);
                r = pd1.y - fmaf(b0, ps1.y, fmaf(b1, qs1.y, b2 * qd1.y)); acc1 = fmaf(r, r, acc1);
            }
        }
    }

    // deterministic block reduction
    __shared__ float red[256];
    __shared__ unsigned isLast;
    const int tid = threadIdx.x;
    red[tid] = acc0 + acc1;
    __syncthreads();
    #pragma unroll
    for (int sOff = 128; sOff > 0; sOff >>= 1) {
        if (tid < sOff) red[tid] += red[tid + sOff];
        __syncthreads();
    }
    if (tid == 0) {
        g_phyPart[blockIdx.x] = red[0];
        __threadfence();
        unsigned v = atomicAdd(&g_done, 1u);
        isLast = (v == gridDim.x - 1) ? 1u : 0u;
    }
    __syncthreads();

    if (isLast) {
        __shared__ double rd2[256];
        __shared__ double rp2[256];
        double sd = 0.0, sp = 0.0;
        for (int i2 = tid; i2 < nDataBlocks; i2 += 256) sd += (double)g_dataPart[i2];
        for (int i2 = tid; i2 < (int)gridDim.x; i2 += 256) sp += (double)g_phyPart[i2];
        rd2[tid] = sd;
        rp2[tid] = sp;
        __syncthreads();
        #pragma unroll
        for (int sOff = 128; sOff > 0; sOff >>= 1) {
            if (tid < sOff) { rd2[tid] += rd2[tid + sOff]; rp2[tid] += rp2[tid + sOff]; }
            __syncthreads();
        }
        if (tid == 0) {
            double data_loss = rd2[0] / ((double)BB * (double)N);
            double phy_loss  = rp2[0] / ((double)BB * (double)E);
            double total = data_loss + LAMBDA_PHY * phy_loss;
            out[0] = (float)total;
            out[1] = (float)data_loss;
            out[2] = (float)phy_loss;
            g_done = 0;   // reset for next graph replay
        }
    }
}

extern "C" void kernel_launch(void* const* d_in, const int* in_sizes, int n_in,
                              void* d_out, int out_size) {
    const float* pred   = (const float*)d_in[0];
    const float* target = (const float*)d_in[1];
    const float* prev   = (const float*)d_in[2];
    const float* c0     = (const float*)d_in[3];
    const float* c1     = (const float*)d_in[4];
    const float* c2     = (const float*)d_in[5];
    const void*  ei     = d_in[6];

    const int N = in_sizes[0] / BB;     // 10000
    const int E = in_sizes[3];          // 320000

    dim3 tb(32, 8);
    int nDataBlocks = (N + 31) / 32;    // 313
    prep_kernel<<<nDataBlocks, tb>>>(pred, target, prev, c0, c1, c2, ei, N, E);

    // single wave: 6 blocks/SM x 148 SMs
    const int phyBlocks = 888;
    edge_phy_kernel<<<phyBlocks, 256>>>(E, N, nDataBlocks, (float*)d_out);
}